// round 2
// baseline (speedup 1.0000x reference)
#include <cuda_runtime.h>
#include <math.h>

#define EPSV 1e-7f

// ---- problem sizes (fixed by the dataset) ----
#define NB 4
#define H0 256
#define W0 448
#define HW0 (H0*W0)      // 114688
#define H1 128
#define W1 224
#define HW1 (H1*W1)      // 28672
#define H2 64
#define W2 112
#define HW2 (H2*W2)      // 7168
#define C0 32
#define C1 64
#define C2 96

// ---- scratch layout (floats) ----
#define OFF_DEN0  0
#define OFF_DEN1  (OFF_DEN0 + NB*HW0)            // 458752
#define OFF_DEN2  (OFF_DEN1 + NB*HW1)            // 573440
#define OFF_DENF  (OFF_DEN2 + NB*HW2)            // 602112
#define OFF_FLOW1 (OFF_DENF + NB*HW0)            // 1060864
#define OFF_MET1  (OFF_FLOW1 + NB*2*HW1)         // 1290240
#define OFF_FLOW2 (OFF_MET1 + NB*HW1)            // 1404928
#define OFF_MET2  (OFF_FLOW2 + NB*2*HW2)         // 1462272
#define SCRATCH_TOTAL (OFF_MET2 + NB*HW2)        // 1490944

__device__ float g_scratch[SCRATCH_TOTAL];

// ---- 2x antialiased bilinear downsample (jax.image.resize, antialias=True) ----
// Interior taps [1/8,3/8,3/8,1/8] over inputs {2o-1..2o+2}; OOB taps dropped and
// weights renormalized (edges become [3/7,3/7,1/7]).
template<int Hi, int Wi>
__global__ void resize_half_kernel(const float* __restrict__ src_flow,
                                   const float* __restrict__ src_met,
                                   float* __restrict__ dst_flow,
                                   float* __restrict__ dst_met,
                                   float flow_scale)
{
    const int Ho = Hi / 2, Wo = Wi / 2;
    int i = blockIdx.x * blockDim.x + threadIdx.x;
    int total = NB * 3 * Ho * Wo;
    if (i >= total) return;
    int p  = i % (Ho * Wo);
    int nc = i / (Ho * Wo);
    int c  = nc % 3;
    int n  = nc / 3;
    int oy = p / Wo, ox = p % Wo;

    const float raw[4] = {0.25f, 0.75f, 0.75f, 0.25f};
    float wy[4], wx[4];
    int   jy[4], jx[4];
    float sy = 0.f, sx = 0.f;
#pragma unroll
    for (int k = 0; k < 4; k++) {
        int j = 2 * oy - 1 + k;
        float w = (j >= 0 && j < Hi) ? raw[k] : 0.f;
        jy[k] = min(max(j, 0), Hi - 1);
        wy[k] = w; sy += w;
    }
#pragma unroll
    for (int k = 0; k < 4; k++) {
        int j = 2 * ox - 1 + k;
        float w = (j >= 0 && j < Wi) ? raw[k] : 0.f;
        jx[k] = min(max(j, 0), Wi - 1);
        wx[k] = w; sx += w;
    }
    float inv = 1.f / (sy * sx);

    const float* src = (c < 2) ? (src_flow + ((size_t)n * 2 + c) * Hi * Wi)
                               : (src_met  + (size_t)n * Hi * Wi);
    float acc = 0.f;
#pragma unroll
    for (int ky = 0; ky < 4; ky++) {
        if (wy[ky] == 0.f) continue;
        const float* row = src + (size_t)jy[ky] * Wi;
        float a = 0.f;
#pragma unroll
        for (int kx = 0; kx < 4; kx++) a += wx[kx] * row[jx[kx]];
        acc += wy[ky] * a;
    }
    acc *= inv;

    if (c < 2) dst_flow[((size_t)n * 2 + c) * Ho * Wo + p] = acc * flow_scale;
    else       dst_met [(size_t)n * Ho * Wo + p] = acc;
}

// ---- bilinear scatter-add splat ----
// num: [NB, C, H, W] accumulator (zeroed), den: [NB, H, W] accumulator,
// hole: [NB, H, W] unit-weight accumulator (for binary_hole), may be disabled.
template<int C, int H, int W, bool HOLE>
__global__ void splat_kernel(const float* __restrict__ feat,
                             const float* __restrict__ flow,
                             const float* __restrict__ metric,
                             float* __restrict__ num,
                             float* __restrict__ den,
                             float* __restrict__ hole,
                             float feat_scale, float flow_scale)
{
    int i = blockIdx.x * blockDim.x + threadIdx.x;
    if (i >= NB * H * W) return;
    int p = i % (H * W);
    int n = i / (H * W);
    int y = p / W, x = p % W;

    const float* fl = flow + (size_t)n * 2 * H * W;
    float gx = (float)x + fl[p]         * flow_scale;
    float gy = (float)y + fl[H * W + p] * flow_scale;
    float x0f = floorf(gx), y0f = floorf(gy);
    float fx = gx - x0f, fy = gy - y0f;
    int x0 = (int)x0f, y0 = (int)y0f;

    float m = metric[(size_t)n * H * W + p];
    float e = expf(fminf(fmaxf(-m, -20.f), 20.f));

    float w[4]  = {(1.f - fx) * (1.f - fy), fx * (1.f - fy),
                   (1.f - fx) * fy,         fx * fy};
    int   xi[4] = {x0, x0 + 1, x0, x0 + 1};
    int   yi[4] = {y0, y0, y0 + 1, y0 + 1};
    int   idx[4];
    bool  valid[4];
#pragma unroll
    for (int k = 0; k < 4; k++) {
        valid[k] = (xi[k] >= 0) & (xi[k] < W) & (yi[k] >= 0) & (yi[k] < H);
        idx[k] = yi[k] * W + xi[k];
    }

    float* denp = den + (size_t)n * H * W;
#pragma unroll
    for (int k = 0; k < 4; k++) {
        if (valid[k]) {
            atomicAdd(denp + idx[k], w[k] * e);
            if (HOLE) atomicAdd(hole + (size_t)n * H * W + idx[k], w[k]);
        }
    }

    const float* fp = feat + (size_t)n * C * H * W + p;
    float* np = num + (size_t)n * C * H * W;
    for (int c = 0; c < C; c++) {
        float v = fp[(size_t)c * H * W] * feat_scale * e;
#pragma unroll
        for (int k = 0; k < 4; k++)
            if (valid[k]) atomicAdd(np + (size_t)c * H * W + idx[k], w[k] * v);
    }
}

// ---- normalize: num /= (den + eps), optional sign flip ----
template<int C, int H, int W>
__global__ void norm_div_kernel(float* __restrict__ num,
                                const float* __restrict__ den, float sign)
{
    int i = blockIdx.x * blockDim.x + threadIdx.x;
    if (i >= NB * C * H * W) return;
    int n = i / (C * H * W);
    int p = i % (H * W);
    num[i] = sign * num[i] / (den[(size_t)n * H * W + p] + EPSV);
}

// ---- binary hole: s -> (s/(s+eps) <= 0.5 ? 1 : 0) ----
__global__ void binarize_kernel(float* __restrict__ s, int total)
{
    int i = blockIdx.x * blockDim.x + threadIdx.x;
    if (i >= total) return;
    float v = s[i];
    float r = v / (v + EPSV);
    s[i] = (r <= 0.5f) ? 1.f : 0.f;
}

extern "C" void kernel_launch(void* const* d_in, const int* in_sizes, int n_in,
                              void* d_out, int out_size)
{
    // metadata order (dict insertion order in setup_inputs):
    // 0:x1_0 1:x2_0 2:x1_1 3:x2_1 4:x1_2 5:x2_2 6:m1t 7:m2t 8:F12 9:F21
    const float* x1_0 = (const float*)d_in[0];
    const float* x1_1 = (const float*)d_in[2];
    const float* x1_2 = (const float*)d_in[4];
    const float* m1t = (const float*)d_in[6];
    const float* m2t = (const float*)d_in[7];
    const float* F12 = (const float*)d_in[8];
    const float* F21 = (const float*)d_in[9];

    float* out = (float*)d_out;
    float* w0  = out;
    float* w1  = w0 + (size_t)NB * C0 * HW0;   // 14,680,064
    float* w2  = w1 + (size_t)NB * C1 * HW1;   // +7,340,032
    float* bm0 = w2 + (size_t)NB * C2 * HW2;   // +2,752,512
    float* bm1 = bm0 + (size_t)NB * HW0;
    float* bm2 = bm1 + (size_t)NB * HW1;
    float* ft2 = bm2 + (size_t)NB * HW2;

    float* scratch = nullptr;
    cudaGetSymbolAddress((void**)&scratch, g_scratch);
    float* den0  = scratch + OFF_DEN0;
    float* den1  = scratch + OFF_DEN1;
    float* den2  = scratch + OFF_DEN2;
    float* denF  = scratch + OFF_DENF;
    float* flow1 = scratch + OFF_FLOW1;
    float* met1  = scratch + OFF_MET1;
    float* flow2 = scratch + OFF_FLOW2;
    float* met2  = scratch + OFF_MET2;

    const int TB = 256;

    // zero accumulators (output regions are accumulated in place)
    cudaMemsetAsync(out, 0, (size_t)out_size * sizeof(float), 0);
    cudaMemsetAsync(scratch, 0, (size_t)OFF_FLOW1 * sizeof(float), 0);

    // chained antialiased 2x downsamples of (flow, metric)
    // level1: flow1 = resize(0.5*F12)*0.5 = 0.25*resize(F12); met1 = resize(m1t)
    {
        int total = NB * 3 * HW1;
        resize_half_kernel<H0, W0><<<(total + TB - 1) / TB, TB>>>(
            F12, m1t, flow1, met1, 0.25f);
    }
    // level2: flow2 = resize(flow1)*0.5; met2 = resize(met1)
    {
        int total = NB * 3 * HW2;
        resize_half_kernel<H1, W1><<<(total + TB - 1) / TB, TB>>>(
            flow1, met1, flow2, met2, 0.5f);
    }

    // splats
    splat_kernel<C0, H0, W0, true><<<(NB * HW0 + TB - 1) / TB, TB>>>(
        x1_0, F12, m1t, w0, den0, bm0, 1.0f, 0.5f);
    splat_kernel<C1, H1, W1, true><<<(NB * HW1 + TB - 1) / TB, TB>>>(
        x1_1, flow1, met1, w1, den1, bm1, 1.0f, 1.0f);
    splat_kernel<C2, H2, W2, true><<<(NB * HW2 + TB - 1) / TB, TB>>>(
        x1_2, flow2, met2, w2, den2, bm2, 1.0f, 1.0f);
    // Ft2 = -softsplat(F2t, F2t, clip(-m2t), soft), F2t = 0.5*F21
    splat_kernel<2, H0, W0, false><<<(NB * HW0 + TB - 1) / TB, TB>>>(
        F21, F21, m2t, ft2, denF, nullptr, 0.5f, 0.5f);

    // normalizations
    norm_div_kernel<C0, H0, W0><<<(NB * C0 * HW0 + TB - 1) / TB, TB>>>(w0, den0, 1.0f);
    norm_div_kernel<C1, H1, W1><<<(NB * C1 * HW1 + TB - 1) / TB, TB>>>(w1, den1, 1.0f);
    norm_div_kernel<C2, H2, W2><<<(NB * C2 * HW2 + TB - 1) / TB, TB>>>(w2, den2, 1.0f);
    norm_div_kernel<2, H0, W0><<<(NB * 2 * HW0 + TB - 1) / TB, TB>>>(ft2, denF, -1.0f);

    // binary hole masks (bm0, bm1, bm2 are contiguous)
    {
        int total = NB * (HW0 + HW1 + HW2);
        binarize_kernel<<<(total + TB - 1) / TB, TB>>>(bm0, total);
    }
}

// round 3
// speedup vs baseline: 1.9032x; 1.9032x over previous
#include <cuda_runtime.h>
#include <math.h>

#define EPSV 1e-7f

// ---- problem sizes (fixed by the dataset) ----
#define NB 4
#define H0 256
#define W0 448
#define HW0 (H0*W0)      // 114688
#define H1 128
#define W1 224
#define HW1 (H1*W1)      // 28672
#define H2 64
#define W2 112
#define HW2 (H2*W2)      // 7168
#define C0 32
#define C1 64
#define C2 96

// padded NHWC strides (floats): C feats + den + hole, padded to mult of 4
#define S0 36
#define S1 68
#define S2 100
#define SF 4

// ---- scratch layout (floats) ----
#define OFF_ACC0  0
#define OFF_ACC1  (OFF_ACC0 + NB*HW0*S0)           // 16,515,072
#define OFF_ACC2  (OFF_ACC1 + NB*HW1*S1)           // 24,313,856
#define OFF_ACCF  (OFF_ACC2 + NB*HW2*S2)           // 27,181,056
#define OFF_FLOW1 (OFF_ACCF + NB*HW0*SF)           // 29,016,064
#define OFF_MET1  (OFF_FLOW1 + NB*2*HW1)
#define OFF_FLOW2 (OFF_MET1 + NB*HW1)
#define OFF_MET2  (OFF_FLOW2 + NB*2*HW2)
#define SCRATCH_TOTAL (OFF_MET2 + NB*HW2)
#define ACC_TOTAL OFF_FLOW1

__device__ __align__(256) float g_scratch[SCRATCH_TOTAL];

__device__ __forceinline__ void red_add_v4(float* p, float a, float b, float c, float d) {
    asm volatile("red.global.add.v4.f32 [%0], {%1,%2,%3,%4};"
                 :: "l"(p), "f"(a), "f"(b), "f"(c), "f"(d) : "memory");
}
__device__ __forceinline__ void red_add_v2(float* p, float a, float b) {
    asm volatile("red.global.add.v2.f32 [%0], {%1,%2};"
                 :: "l"(p), "f"(a), "f"(b) : "memory");
}

// ---- 2x antialiased bilinear downsample (jax.image.resize, antialias=True) ----
template<int Hi, int Wi>
__global__ void resize_half_kernel(const float* __restrict__ src_flow,
                                   const float* __restrict__ src_met,
                                   float* __restrict__ dst_flow,
                                   float* __restrict__ dst_met,
                                   float flow_scale)
{
    const int Ho = Hi / 2, Wo = Wi / 2;
    int i = blockIdx.x * blockDim.x + threadIdx.x;
    int total = NB * 3 * Ho * Wo;
    if (i >= total) return;
    int p  = i % (Ho * Wo);
    int nc = i / (Ho * Wo);
    int c  = nc % 3;
    int n  = nc / 3;
    int oy = p / Wo, ox = p % Wo;

    const float raw[4] = {0.25f, 0.75f, 0.75f, 0.25f};
    float wy[4], wx[4];
    int   jy[4], jx[4];
    float sy = 0.f, sx = 0.f;
#pragma unroll
    for (int k = 0; k < 4; k++) {
        int j = 2 * oy - 1 + k;
        float w = (j >= 0 && j < Hi) ? raw[k] : 0.f;
        jy[k] = min(max(j, 0), Hi - 1);
        wy[k] = w; sy += w;
    }
#pragma unroll
    for (int k = 0; k < 4; k++) {
        int j = 2 * ox - 1 + k;
        float w = (j >= 0 && j < Wi) ? raw[k] : 0.f;
        jx[k] = min(max(j, 0), Wi - 1);
        wx[k] = w; sx += w;
    }
    float inv = 1.f / (sy * sx);

    const float* src = (c < 2) ? (src_flow + ((size_t)n * 2 + c) * Hi * Wi)
                               : (src_met  + (size_t)n * Hi * Wi);
    float acc = 0.f;
#pragma unroll
    for (int ky = 0; ky < 4; ky++) {
        if (wy[ky] == 0.f) continue;
        const float* row = src + (size_t)jy[ky] * Wi;
        float a = 0.f;
#pragma unroll
        for (int kx = 0; kx < 4; kx++) a += wx[kx] * row[jx[kx]];
        acc += wy[ky] * a;
    }
    acc *= inv;

    if (c < 2) dst_flow[((size_t)n * 2 + c) * Ho * Wo + p] = acc * flow_scale;
    else       dst_met [(size_t)n * Ho * Wo + p] = acc;
}

// ---- NHWC splat with vector reductions ----
// acc layout: [NB*H*W][SP] where [0..C) feats, [C]=den, [C+1]=hole.
// Each thread handles one pixel and a group of 8 channels.
template<int C, int H, int W, int SP>
__global__ void splat_nhwc_kernel(const float* __restrict__ feat,
                                  const float* __restrict__ flow,
                                  const float* __restrict__ metric,
                                  float* __restrict__ acc,
                                  float flow_scale)
{
    constexpr int P = NB * H * W;
    constexpr int NGRP = C / 8;
    int i = blockIdx.x * blockDim.x + threadIdx.x;
    if (i >= P * NGRP) return;
    int pix = i % P;         // warps: consecutive pixels, uniform group
    int g   = i / P;
    int n = pix / (H * W);
    int p = pix % (H * W);
    int y = p / W, x = p % W;

    const float* fl = flow + (size_t)n * 2 * H * W;
    float gx = (float)x + fl[p]         * flow_scale;
    float gy = (float)y + fl[H * W + p] * flow_scale;
    float x0f = floorf(gx), y0f = floorf(gy);
    float fx = gx - x0f, fy = gy - y0f;
    int x0 = (int)x0f, y0 = (int)y0f;

    float m = metric[(size_t)n * H * W + p];
    float e = __expf(fminf(fmaxf(-m, -20.f), 20.f));

    float w[4]  = {(1.f - fx) * (1.f - fy), fx * (1.f - fy),
                   (1.f - fx) * fy,         fx * fy};
    int   xi[2] = {x0, x0 + 1};
    int   yi[2] = {y0, y0 + 1};
    bool  vx[2] = {x0 >= 0 && x0 < W, x0 + 1 >= 0 && x0 + 1 < W};
    bool  vy[2] = {y0 >= 0 && y0 < H, y0 + 1 >= 0 && y0 + 1 < H};

    // load 8 channels, pre-scaled by e
    int c0 = g * 8;
    const float* fp = feat + (size_t)n * C * H * W + (size_t)c0 * H * W + p;
    float v[8];
#pragma unroll
    for (int j = 0; j < 8; j++) v[j] = fp[(size_t)j * H * W] * e;

#pragma unroll
    for (int ky = 0; ky < 2; ky++) {
#pragma unroll
        for (int kx = 0; kx < 2; kx++) {
            if (!(vx[kx] && vy[ky])) continue;
            float wk = w[ky * 2 + kx];
            float* base = acc + ((size_t)n * H * W + yi[ky] * W + xi[kx]) * SP;
            red_add_v4(base + c0,     wk * v[0], wk * v[1], wk * v[2], wk * v[3]);
            red_add_v4(base + c0 + 4, wk * v[4], wk * v[5], wk * v[6], wk * v[7]);
            if (g == 0) red_add_v2(base + C, wk * e, wk);
        }
    }
}

// ---- flow self-splat (Ft2), stride-4 NHWC accumulator ----
__global__ void splat_flow_kernel(const float* __restrict__ F21,
                                  const float* __restrict__ m2t,
                                  float* __restrict__ acc)
{
    constexpr int H = H0, W = W0;
    constexpr int P = NB * H * W;
    int i = blockIdx.x * blockDim.x + threadIdx.x;
    if (i >= P) return;
    int n = i / (H * W);
    int p = i % (H * W);
    int y = p / W, x = p % W;

    const float* fl = F21 + (size_t)n * 2 * H * W;
    float ux = fl[p] * 0.5f;           // F2t = 0.5*F21
    float uy = fl[H * W + p] * 0.5f;
    float gx = (float)x + ux;
    float gy = (float)y + uy;
    float x0f = floorf(gx), y0f = floorf(gy);
    float fx = gx - x0f, fy = gy - y0f;
    int x0 = (int)x0f, y0 = (int)y0f;

    float m = m2t[(size_t)n * H * W + p];
    float e = __expf(fminf(fmaxf(-m, -20.f), 20.f));
    float vx0 = ux * e, vy0 = uy * e;

    float w[4]  = {(1.f - fx) * (1.f - fy), fx * (1.f - fy),
                   (1.f - fx) * fy,         fx * fy};
    int   xi[2] = {x0, x0 + 1};
    int   yi[2] = {y0, y0 + 1};
    bool  bx[2] = {x0 >= 0 && x0 < W, x0 + 1 >= 0 && x0 + 1 < W};
    bool  by[2] = {y0 >= 0 && y0 < H, y0 + 1 >= 0 && y0 + 1 < H};

#pragma unroll
    for (int ky = 0; ky < 2; ky++) {
#pragma unroll
        for (int kx = 0; kx < 2; kx++) {
            if (!(bx[kx] && by[ky])) continue;
            float wk = w[ky * 2 + kx];
            float* base = acc + ((size_t)n * H * W + yi[ky] * W + xi[kx]) * SF;
            red_add_v4(base, wk * vx0, wk * vy0, wk * e, 0.f);
        }
    }
}

// ---- normalize + NHWC->NCHW transpose + hole binarize ----
// One block handles TP=32 pixels (within one n). smem tile of 32*SP floats.
template<int C, int H, int W, int SP>
__global__ void norm_transpose_kernel(const float* __restrict__ acc,
                                      float* __restrict__ out,
                                      float* __restrict__ bm)
{
    constexpr int TP = 32;
    __shared__ float tile[TP * SP];
    __shared__ float inv[TP];

    int gp0 = blockIdx.x * TP;                 // global pixel base (n*HW+p)
    const float* src = acc + (size_t)gp0 * SP;
    for (int j = threadIdx.x; j < TP * SP; j += blockDim.x)
        tile[j] = src[j];
    __syncthreads();
    if (threadIdx.x < TP)
        inv[threadIdx.x] = 1.f / (tile[threadIdx.x * SP + C] + EPSV);
    __syncthreads();

    int n  = gp0 / (H * W);
    int p0 = gp0 % (H * W);
    float* outn = out + (size_t)n * C * H * W;
    for (int j = threadIdx.x; j < C * TP; j += blockDim.x) {
        int pl = j & 31;
        int c  = j >> 5;
        outn[(size_t)c * H * W + p0 + pl] = tile[pl * SP + c] * inv[pl];
        if (c == 0) {
            float h = tile[pl * SP + C + 1];
            float r = h / (h + EPSV);
            bm[(size_t)gp0 + pl] = (r <= 0.5f) ? 1.f : 0.f;
        }
    }
}

// ---- normalize Ft2: ft2 = -num/(den+eps) ----
__global__ void norm_flow_kernel(const float* __restrict__ acc,
                                 float* __restrict__ ft2)
{
    constexpr int P = NB * HW0;
    int i = blockIdx.x * blockDim.x + threadIdx.x;
    if (i >= P) return;
    float4 a = reinterpret_cast<const float4*>(acc)[i];
    float inv = 1.f / (a.z + EPSV);
    int n = i / HW0;
    int p = i % HW0;
    float* dst = ft2 + (size_t)n * 2 * HW0;
    dst[p]       = -a.x * inv;
    dst[HW0 + p] = -a.y * inv;
}

extern "C" void kernel_launch(void* const* d_in, const int* in_sizes, int n_in,
                              void* d_out, int out_size)
{
    // metadata order: 0:x1_0 1:x2_0 2:x1_1 3:x2_1 4:x1_2 5:x2_2 6:m1t 7:m2t 8:F12 9:F21
    const float* x1_0 = (const float*)d_in[0];
    const float* x1_1 = (const float*)d_in[2];
    const float* x1_2 = (const float*)d_in[4];
    const float* m1t = (const float*)d_in[6];
    const float* m2t = (const float*)d_in[7];
    const float* F12 = (const float*)d_in[8];
    const float* F21 = (const float*)d_in[9];

    float* out = (float*)d_out;
    float* w0  = out;
    float* w1  = w0 + (size_t)NB * C0 * HW0;
    float* w2  = w1 + (size_t)NB * C1 * HW1;
    float* bm0 = w2 + (size_t)NB * C2 * HW2;
    float* bm1 = bm0 + (size_t)NB * HW0;
    float* bm2 = bm1 + (size_t)NB * HW1;
    float* ft2 = bm2 + (size_t)NB * HW2;

    float* scratch = nullptr;
    cudaGetSymbolAddress((void**)&scratch, g_scratch);
    float* acc0  = scratch + OFF_ACC0;
    float* acc1  = scratch + OFF_ACC1;
    float* acc2  = scratch + OFF_ACC2;
    float* accF  = scratch + OFF_ACCF;
    float* flow1 = scratch + OFF_FLOW1;
    float* met1  = scratch + OFF_MET1;
    float* flow2 = scratch + OFF_FLOW2;
    float* met2  = scratch + OFF_MET2;

    const int TB = 256;

    // zero the NHWC accumulators
    cudaMemsetAsync(scratch, 0, (size_t)ACC_TOTAL * sizeof(float), 0);

    // chained antialiased 2x downsamples of (flow, metric)
    {
        int total = NB * 3 * HW1;
        resize_half_kernel<H0, W0><<<(total + TB - 1) / TB, TB>>>(
            F12, m1t, flow1, met1, 0.25f);
    }
    {
        int total = NB * 3 * HW2;
        resize_half_kernel<H1, W1><<<(total + TB - 1) / TB, TB>>>(
            flow1, met1, flow2, met2, 0.5f);
    }

    // splats (NHWC accumulation, vector reds)
    {
        int total = NB * HW0 * (C0 / 8);
        splat_nhwc_kernel<C0, H0, W0, S0><<<(total + TB - 1) / TB, TB>>>(
            x1_0, F12, m1t, acc0, 0.5f);
    }
    {
        int total = NB * HW1 * (C1 / 8);
        splat_nhwc_kernel<C1, H1, W1, S1><<<(total + TB - 1) / TB, TB>>>(
            x1_1, flow1, met1, acc1, 1.0f);
    }
    {
        int total = NB * HW2 * (C2 / 8);
        splat_nhwc_kernel<C2, H2, W2, S2><<<(total + TB - 1) / TB, TB>>>(
            x1_2, flow2, met2, acc2, 1.0f);
    }
    {
        int total = NB * HW0;
        splat_flow_kernel<<<(total + TB - 1) / TB, TB>>>(F21, m2t, accF);
    }

    // normalize + transpose + binarize
    norm_transpose_kernel<C0, H0, W0, S0><<<NB * HW0 / 32, TB>>>(acc0, w0, bm0);
    norm_transpose_kernel<C1, H1, W1, S1><<<NB * HW1 / 32, TB>>>(acc1, w1, bm1);
    norm_transpose_kernel<C2, H2, W2, S2><<<NB * HW2 / 32, TB>>>(acc2, w2, bm2);
    norm_flow_kernel<<<(NB * HW0 + TB - 1) / TB, TB>>>(accF, ft2);
}